// round 6
// baseline (speedup 1.0000x reference)
#include <cuda_runtime.h>
#include <math.h>

#define NN 50000
#define NR 500
#define NE 600000
#define F 128
#define NH 4

#define NODE_WARPS ((NN + 3) / 4)            // 12500 (4 nodes per warp)
#define NODE_BLOCKS ((NODE_WARPS + 7) / 8)   // 1563
#define REL_BLOCKS ((NR + 7) / 8)            // 63
#define HIST_BLOCKS ((NE + 255) / 256)       // 2344
#define SCAN_B 256
#define SCAN_NB ((NN + SCAN_B - 1) / SCAN_B) // 196

// ---------------- static device scratch (no allocations allowed) ----------------
__device__ int    g_is64;
__device__ int    g_counts[NN];
__device__ int    g_offsets[NN];
__device__ int    g_cursor[NN];
__device__ int    g_bsum[SCAN_NB];
__device__ int2   g_sr[NE];        // CSR-ordered (src, rel) per edge
__device__ float4 g_ee[NE];        // CSR-ordered per-edge exp weights (4 heads)
__device__ float4 g_stab[NN];      // per-node logit contribution per head
__device__ float4 g_rtab[NR];      // per-relation logit contribution per head
__device__ float  g_cumw[NH * F];  // cumulative diagonal scale per head
__device__ float  g_aeff[NH * F];  // cumw * a_src
__device__ float  g_arel[NH * F];  // a_rel

__device__ __forceinline__ int edge_val(const void* A, long long idx, int is64) {
    if (is64) return (int)((const long long*)A)[idx];
    return ((const int*)A)[idx];
}

// --------- packed f32x2 helpers (FFMA2 is PTX-only; ptxas won't auto-fuse) ---------
__device__ __forceinline__ void fma2(unsigned long long& acc,
                                     unsigned long long a, unsigned long long b) {
    asm("fma.rn.f32x2 %0, %1, %2, %3;" : "=l"(acc) : "l"(a), "l"(b), "l"(acc));
}
__device__ __forceinline__ void add2(unsigned long long& acc, unsigned long long a) {
    asm("add.rn.f32x2 %0, %1, %2;" : "=l"(acc) : "l"(a), "l"(acc));
}
__device__ __forceinline__ unsigned long long pack2(float lo, float hi) {
    unsigned long long r;
    asm("mov.b64 %0, {%1, %2};" : "=l"(r) : "f"(lo), "f"(hi));
    return r;
}
__device__ __forceinline__ void unpack2(float& lo, float& hi, unsigned long long v) {
    asm("mov.b64 {%0, %1}, %2;" : "=f"(lo), "=f"(hi) : "l"(v));
}

// Fused: zero counts (all blocks) + dtype detect (b0t0) + param prep (b0, t<128).
__global__ void k_init(const void* __restrict__ A,
                       const float* __restrict__ w,
                       const float* __restrict__ asd) {
    int i = blockIdx.x * blockDim.x + threadIdx.x;
    if (i < NN) g_counts[i] = 0;
    if (blockIdx.x == 0) {
        if (threadIdx.x == 0) {
            const int* a32 = (const int*)A;
            // dst starts with arange(NN): int64 LE -> words [0,0,1,0,...]; int32 -> [0,1,2,...]
            g_is64 = (a32[1] == 0 && a32[2] == 1) ? 1 : 0;
        }
        if (threadIdx.x < F) {
            int c = threadIdx.x;
            float cw = 1.0f;
#pragma unroll
            for (int h = 0; h < NH; h++) {
                if (h > 0) cw *= w[(h - 1) * F + c];
                g_cumw[h * F + c] = cw;
                g_aeff[h * F + c] = cw * asd[h * 2 * F + c];  // a_src_dst[h,0,c,0]
                g_arel[h * F + c] = asd[h * 2 * F + F + c];   // a_src_dst[h,1,c,0]
            }
        }
    }
}

// Fused: node logit tables | relation logit tables | dst histogram (block-range split).
__global__ void __launch_bounds__(256) k_logits_hist(const float* __restrict__ h,
                                                     const float* __restrict__ inputr,
                                                     const void* __restrict__ A) {
    int wib = threadIdx.x >> 5;
    int lane = threadIdx.x & 31;
    if (blockIdx.x < NODE_BLOCKS) {
        int wid = blockIdx.x * 8 + wib;
        int nb = wid * 4;
        if (nb >= NN) return;
        float4 a[NH];
#pragma unroll
        for (int i = 0; i < NH; i++)
            a[i] = *(const float4*)(g_aeff + i * F + lane * 4);
        float4 hv[4];
#pragma unroll
        for (int k = 0; k < 4; k++)
            hv[k] = *(const float4*)(h + (size_t)(nb + k) * F + lane * 4);
        float acc[4][NH];
#pragma unroll
        for (int k = 0; k < 4; k++)
#pragma unroll
            for (int i = 0; i < NH; i++)
                acc[k][i] = hv[k].x * a[i].x + hv[k].y * a[i].y +
                            hv[k].z * a[i].z + hv[k].w * a[i].w;
#pragma unroll
        for (int off = 16; off > 0; off >>= 1)
#pragma unroll
            for (int k = 0; k < 4; k++)
#pragma unroll
                for (int i = 0; i < NH; i++)
                    acc[k][i] += __shfl_xor_sync(0xffffffffu, acc[k][i], off);
        if (lane == 0) {
#pragma unroll
            for (int k = 0; k < 4; k++)
                g_stab[nb + k] = make_float4(acc[k][0], acc[k][1], acc[k][2], acc[k][3]);
        }
    } else if (blockIdx.x < NODE_BLOCKS + REL_BLOCKS) {
        int rl = (blockIdx.x - NODE_BLOCKS) * 8 + wib;
        if (rl >= NR) return;
        float4 rv = *(const float4*)(inputr + (size_t)rl * F + lane * 4);
        float acc[NH];
#pragma unroll
        for (int i = 0; i < NH; i++) {
            float4 a = *(const float4*)(g_arel + i * F + lane * 4);
            acc[i] = rv.x * a.x + rv.y * a.y + rv.z * a.z + rv.w * a.w;
        }
#pragma unroll
        for (int off = 16; off > 0; off >>= 1)
#pragma unroll
            for (int i = 0; i < NH; i++)
                acc[i] += __shfl_xor_sync(0xffffffffu, acc[i], off);
        if (lane == 0) g_rtab[rl] = make_float4(acc[0], acc[1], acc[2], acc[3]);
    } else {
        int e = (blockIdx.x - NODE_BLOCKS - REL_BLOCKS) * 256 + threadIdx.x;
        if (e >= NE) return;
        int dst = edge_val(A, e, g_is64);
        atomicAdd(&g_counts[dst], 1);
    }
}

// -------- hierarchical scan: per-block sums, then local scans w/ inline prefix --------
__global__ void __launch_bounds__(SCAN_B) k_scan1() {
    __shared__ int sh[SCAN_B / 32];
    int i = blockIdx.x * SCAN_B + threadIdx.x;
    int v = (i < NN) ? g_counts[i] : 0;
#pragma unroll
    for (int off = 16; off > 0; off >>= 1)
        v += __shfl_xor_sync(0xffffffffu, v, off);
    if ((threadIdx.x & 31) == 0) sh[threadIdx.x >> 5] = v;
    __syncthreads();
    if (threadIdx.x == 0) {
        int s = 0;
#pragma unroll
        for (int k = 0; k < SCAN_B / 32; k++) s += sh[k];
        g_bsum[blockIdx.x] = s;
    }
}

// Local exclusive scan; each block computes its own offset by reducing the
// g_bsum prefix (196 ints — trivial) instead of a separate middle kernel.
__global__ void __launch_bounds__(SCAN_B) k_scan3() {
    __shared__ int sh[SCAN_B];
    __shared__ int swarp[SCAN_B / 32];
    int t = threadIdx.x;
    // block-offset reduce: sum g_bsum[0 .. blockIdx.x)
    int p = (t < blockIdx.x && t < SCAN_NB) ? g_bsum[t] : 0;
#pragma unroll
    for (int off = 16; off > 0; off >>= 1)
        p += __shfl_xor_sync(0xffffffffu, p, off);
    if ((t & 31) == 0) swarp[t >> 5] = p;

    int i = blockIdx.x * SCAN_B + t;
    int v = (i < NN) ? g_counts[i] : 0;
    sh[t] = v;
    __syncthreads();
    int base = 0;
#pragma unroll
    for (int k = 0; k < SCAN_B / 32; k++) base += swarp[k];
#pragma unroll
    for (int off = 1; off < SCAN_B; off <<= 1) {
        int u = (t >= off) ? sh[t - off] : 0;
        __syncthreads();
        sh[t] += u;
        __syncthreads();
    }
    if (i < NN) {
        int o = base + sh[t] - v;  // exclusive prefix
        g_offsets[i] = o;
        g_cursor[i] = o;
    }
}

// Scatter edges into CSR order; compute 4-head exp weights per edge.
__global__ void k_scatter(const void* __restrict__ A) {
    int e = blockIdx.x * blockDim.x + threadIdx.x;
    if (e >= NE) return;
    int is64 = g_is64;
    int dst = edge_val(A, e, is64);
    int rel = edge_val(A, (long long)NE + e, is64);
    int src = edge_val(A, 2LL * NE + e, is64);
    float4 s = g_stab[src];
    float4 r = g_rtab[rel];
    float lx = s.x + r.x; lx = (lx > 0.0f) ? lx : 0.2f * lx;
    float ly = s.y + r.y; ly = (ly > 0.0f) ? ly : 0.2f * ly;
    float lz = s.z + r.z; lz = (lz > 0.0f) ? lz : 0.2f * lz;
    float lw = s.w + r.w; lw = (lw > 0.0f) ? lw : 0.2f * lw;
    float4 ee = make_float4(expf(-lx), expf(-ly), expf(-lz), expf(-lw));
    int pos = atomicAdd(&g_cursor[dst], 1);
    g_sr[pos] = make_int2(src, rel);
    g_ee[pos] = ee;
}

typedef unsigned long long u64;

// Packed accumulate: 16 fma.f32x2 + 2 add.f32x2 on FMA pipe (vs 36 scalar FFMA),
// packs go to ALU pipe.
#define ACCUM2(ee, hp, rp)                                                   \
    {                                                                        \
        u64 w2[4] = {pack2(ee.x, ee.x), pack2(ee.y, ee.y),                   \
                     pack2(ee.z, ee.z), pack2(ee.w, ee.w)};                  \
        add2(rs01, pack2(ee.x, ee.y));                                       \
        add2(rs23, pack2(ee.z, ee.w));                                       \
        _Pragma("unroll") for (int i = 0; i < NH; i++) {                     \
            fma2(accH[i][0], w2[i], hp.x);                                   \
            fma2(accH[i][1], w2[i], hp.y);                                   \
            fma2(accR[i][0], w2[i], rp.x);                                   \
            fma2(accR[i][1], w2[i], rp.y);                                   \
        }                                                                    \
    }

// Aggregation: one warp per node, lane owns 4 feature columns (two f32x2 pairs).
__global__ void __launch_bounds__(256) k_agg(const float* __restrict__ h,
                                             const float* __restrict__ inputr,
                                             float* __restrict__ out) {
    int gtid = blockIdx.x * blockDim.x + threadIdx.x;
    int node = gtid >> 5;
    int lane = threadIdx.x & 31;
    if (node >= NN) return;

    int start = g_offsets[node];
    int end = start + g_counts[node];

    u64 accH[NH][2];
    u64 accR[NH][2];
    u64 rs01 = 0, rs23 = 0;  // 0x0 == packed (0.0f, 0.0f)
#pragma unroll
    for (int i = 0; i < NH; i++) {
        accH[i][0] = 0; accH[i][1] = 0;
        accR[i][0] = 0; accR[i][1] = 0;
    }

    int j = start;
#pragma unroll 1
    for (; j + 1 < end; j += 2) {
        int2 sa = g_sr[j];
        int2 sb = g_sr[j + 1];
        float4 ea = g_ee[j];
        float4 eb = g_ee[j + 1];
        ulonglong2 ha = *(const ulonglong2*)(h + (size_t)sa.x * F + lane * 4);
        ulonglong2 ra = *(const ulonglong2*)(inputr + (size_t)sa.y * F + lane * 4);
        ulonglong2 hb = *(const ulonglong2*)(h + (size_t)sb.x * F + lane * 4);
        ulonglong2 rb = *(const ulonglong2*)(inputr + (size_t)sb.y * F + lane * 4);
        ACCUM2(ea, ha, ra);
        ACCUM2(eb, hb, rb);
    }
    if (j < end) {
        int2 sa = g_sr[j];
        float4 ea = g_ee[j];
        ulonglong2 ha = *(const ulonglong2*)(h + (size_t)sa.x * F + lane * 4);
        ulonglong2 ra = *(const ulonglong2*)(inputr + (size_t)sa.y * F + lane * 4);
        ACCUM2(ea, ha, ra);
    }

    float rs[NH];
    unpack2(rs[0], rs[1], rs01);
    unpack2(rs[2], rs[3], rs23);

#pragma unroll
    for (int i = 0; i < NH; i++) {
        float4 cw = *(const float4*)(g_cumw + i * F + lane * 4);
        float inv = 1.0f / rs[i];
        float h0, h1, h2, h3, r0, r1, r2, r3;
        unpack2(h0, h1, accH[i][0]);
        unpack2(h2, h3, accH[i][1]);
        unpack2(r0, r1, accR[i][0]);
        unpack2(r2, r3, accR[i][1]);
        float4 o;
        o.x = (cw.x * h0 - r0) * inv;
        o.y = (cw.y * h1 - r1) * inv;
        o.z = (cw.z * h2 - r2) * inv;
        o.w = (cw.w * h3 - r3) * inv;
        __stcs((float4*)(out + (size_t)i * NN * F + (size_t)node * F + lane * 4), o);
    }
}

extern "C" void kernel_launch(void* const* d_in, const int* in_sizes, int n_in,
                              void* d_out, int out_size) {
    const float* h      = (const float*)d_in[0];
    const float* inputr = (const float*)d_in[1];
    const float* w      = (const float*)d_in[2];
    const float* asd    = (const float*)d_in[3];
    const void*  A      = d_in[4];
    float* out = (float*)d_out;

    k_init<<<(NN + 255) / 256, 256>>>(A, w, asd);
    k_logits_hist<<<NODE_BLOCKS + REL_BLOCKS + HIST_BLOCKS, 256>>>(h, inputr, A);
    k_scan1<<<SCAN_NB, SCAN_B>>>();
    k_scan3<<<SCAN_NB, SCAN_B>>>();
    k_scatter<<<(NE + 255) / 256, 256>>>(A);
    k_agg<<<(NN * 32 + 255) / 256, 256>>>(h, inputr, out);
}

// round 10
// speedup vs baseline: 1.1246x; 1.1246x over previous
#include <cuda_runtime.h>
#include <math.h>

#define NN 50000
#define NR 500
#define NE 600000
#define F 128
#define NH 4

#define NODE_WARPS ((NN + 3) / 4)            // 12500 (4 nodes per warp)
#define NODE_BLOCKS ((NODE_WARPS + 7) / 8)   // 1563
#define REL_BLOCKS ((NR + 7) / 8)            // 63
#define HIST_BLOCKS ((NE + 255) / 256)       // 2344
#define SCAN_B 256
#define SCAN_NB ((NN + SCAN_B - 1) / SCAN_B) // 196

// ---------------- static device scratch (no allocations allowed) ----------------
__device__ int    g_is64;
__device__ int    g_counts[NN];
__device__ int    g_offsets[NN];
__device__ int    g_cursor[NN];
__device__ int    g_bsum[SCAN_NB];
__device__ int2   g_sr[NE];        // CSR-ordered (src, rel) per edge
__device__ float4 g_ee[NE];        // CSR-ordered per-edge exp weights (4 heads)
__device__ float4 g_stab[NN];      // per-node logit contribution per head
__device__ float4 g_rtab[NR];      // per-relation logit contribution per head
__device__ float  g_cumw[NH * F];  // cumulative diagonal scale per head
__device__ float  g_aeff[NH * F];  // cumw * a_src
__device__ float  g_arel[NH * F];  // a_rel

__device__ __forceinline__ int edge_val(const void* A, long long idx, int is64) {
    if (is64) return (int)((const long long*)A)[idx];
    return ((const int*)A)[idx];
}

// Fused: zero counts (all blocks) + dtype detect (b0t0) + param prep (b0, t<128).
__global__ void k_init(const void* __restrict__ A,
                       const float* __restrict__ w,
                       const float* __restrict__ asd) {
    int i = blockIdx.x * blockDim.x + threadIdx.x;
    if (i < NN) g_counts[i] = 0;
    if (blockIdx.x == 0) {
        if (threadIdx.x == 0) {
            const int* a32 = (const int*)A;
            // dst starts with arange(NN): int64 LE -> words [0,0,1,0,...]; int32 -> [0,1,2,...]
            g_is64 = (a32[1] == 0 && a32[2] == 1) ? 1 : 0;
        }
        if (threadIdx.x < F) {
            int c = threadIdx.x;
            float cw = 1.0f;
#pragma unroll
            for (int h = 0; h < NH; h++) {
                if (h > 0) cw *= w[(h - 1) * F + c];
                g_cumw[h * F + c] = cw;
                g_aeff[h * F + c] = cw * asd[h * 2 * F + c];  // a_src_dst[h,0,c,0]
                g_arel[h * F + c] = asd[h * 2 * F + F + c];   // a_src_dst[h,1,c,0]
            }
        }
    }
}

// Fused: node logit tables | relation logit tables | dst histogram (block-range split).
__global__ void __launch_bounds__(256) k_logits_hist(const float* __restrict__ h,
                                                     const float* __restrict__ inputr,
                                                     const void* __restrict__ A) {
    int wib = threadIdx.x >> 5;
    int lane = threadIdx.x & 31;
    if (blockIdx.x < NODE_BLOCKS) {
        int wid = blockIdx.x * 8 + wib;
        int nb = wid * 4;
        if (nb >= NN) return;
        float4 a[NH];
#pragma unroll
        for (int i = 0; i < NH; i++)
            a[i] = *(const float4*)(g_aeff + i * F + lane * 4);
        float4 hv[4];
#pragma unroll
        for (int k = 0; k < 4; k++)
            hv[k] = *(const float4*)(h + (size_t)(nb + k) * F + lane * 4);
        float acc[4][NH];
#pragma unroll
        for (int k = 0; k < 4; k++)
#pragma unroll
            for (int i = 0; i < NH; i++)
                acc[k][i] = hv[k].x * a[i].x + hv[k].y * a[i].y +
                            hv[k].z * a[i].z + hv[k].w * a[i].w;
#pragma unroll
        for (int off = 16; off > 0; off >>= 1)
#pragma unroll
            for (int k = 0; k < 4; k++)
#pragma unroll
                for (int i = 0; i < NH; i++)
                    acc[k][i] += __shfl_xor_sync(0xffffffffu, acc[k][i], off);
        if (lane == 0) {
#pragma unroll
            for (int k = 0; k < 4; k++)
                g_stab[nb + k] = make_float4(acc[k][0], acc[k][1], acc[k][2], acc[k][3]);
        }
    } else if (blockIdx.x < NODE_BLOCKS + REL_BLOCKS) {
        int rl = (blockIdx.x - NODE_BLOCKS) * 8 + wib;
        if (rl >= NR) return;
        float4 rv = *(const float4*)(inputr + (size_t)rl * F + lane * 4);
        float acc[NH];
#pragma unroll
        for (int i = 0; i < NH; i++) {
            float4 a = *(const float4*)(g_arel + i * F + lane * 4);
            acc[i] = rv.x * a.x + rv.y * a.y + rv.z * a.z + rv.w * a.w;
        }
#pragma unroll
        for (int off = 16; off > 0; off >>= 1)
#pragma unroll
            for (int i = 0; i < NH; i++)
                acc[i] += __shfl_xor_sync(0xffffffffu, acc[i], off);
        if (lane == 0) g_rtab[rl] = make_float4(acc[0], acc[1], acc[2], acc[3]);
    } else {
        int e = (blockIdx.x - NODE_BLOCKS - REL_BLOCKS) * 256 + threadIdx.x;
        if (e >= NE) return;
        int dst = edge_val(A, e, g_is64);
        atomicAdd(&g_counts[dst], 1);
    }
}

// -------- hierarchical scan: per-block sums, then local scans w/ inline prefix --------
__global__ void __launch_bounds__(SCAN_B) k_scan1() {
    __shared__ int sh[SCAN_B / 32];
    int i = blockIdx.x * SCAN_B + threadIdx.x;
    int v = (i < NN) ? g_counts[i] : 0;
#pragma unroll
    for (int off = 16; off > 0; off >>= 1)
        v += __shfl_xor_sync(0xffffffffu, v, off);
    if ((threadIdx.x & 31) == 0) sh[threadIdx.x >> 5] = v;
    __syncthreads();
    if (threadIdx.x == 0) {
        int s = 0;
#pragma unroll
        for (int k = 0; k < SCAN_B / 32; k++) s += sh[k];
        g_bsum[blockIdx.x] = s;
    }
}

// Local exclusive scan; each block computes its own offset by reducing the
// g_bsum prefix (196 ints — trivial) instead of a separate middle kernel.
__global__ void __launch_bounds__(SCAN_B) k_scan3() {
    __shared__ int sh[SCAN_B];
    __shared__ int swarp[SCAN_B / 32];
    int t = threadIdx.x;
    // block-offset reduce: sum g_bsum[0 .. blockIdx.x)
    int p = (t < blockIdx.x && t < SCAN_NB) ? g_bsum[t] : 0;
#pragma unroll
    for (int off = 16; off > 0; off >>= 1)
        p += __shfl_xor_sync(0xffffffffu, p, off);
    if ((t & 31) == 0) swarp[t >> 5] = p;

    int i = blockIdx.x * SCAN_B + t;
    int v = (i < NN) ? g_counts[i] : 0;
    sh[t] = v;
    __syncthreads();
    int base = 0;
#pragma unroll
    for (int k = 0; k < SCAN_B / 32; k++) base += swarp[k];
#pragma unroll
    for (int off = 1; off < SCAN_B; off <<= 1) {
        int u = (t >= off) ? sh[t - off] : 0;
        __syncthreads();
        sh[t] += u;
        __syncthreads();
    }
    if (i < NN) {
        int o = base + sh[t] - v;  // exclusive prefix
        g_offsets[i] = o;
        g_cursor[i] = o;
    }
}

// Scatter edges into CSR order; compute 4-head exp weights per edge.
__global__ void k_scatter(const void* __restrict__ A) {
    int e = blockIdx.x * blockDim.x + threadIdx.x;
    if (e >= NE) return;
    int is64 = g_is64;
    int dst = edge_val(A, e, is64);
    int rel = edge_val(A, (long long)NE + e, is64);
    int src = edge_val(A, 2LL * NE + e, is64);
    float4 s = g_stab[src];
    float4 r = g_rtab[rel];
    float lx = s.x + r.x; lx = (lx > 0.0f) ? lx : 0.2f * lx;
    float ly = s.y + r.y; ly = (ly > 0.0f) ? ly : 0.2f * ly;
    float lz = s.z + r.z; lz = (lz > 0.0f) ? lz : 0.2f * lz;
    float lw = s.w + r.w; lw = (lw > 0.0f) ? lw : 0.2f * lw;
    float4 ee = make_float4(expf(-lx), expf(-ly), expf(-lz), expf(-lw));
    int pos = atomicAdd(&g_cursor[dst], 1);
    g_sr[pos] = make_int2(src, rel);
    g_ee[pos] = ee;
}

#define ACCUM(ee, hv, rv)                                                   \
    {                                                                       \
        float eev[4] = {ee.x, ee.y, ee.z, ee.w};                            \
        _Pragma("unroll") for (int i = 0; i < NH; i++) {                    \
            float wt = eev[i];                                              \
            rs[i] += wt;                                                    \
            accH[i][0] += wt * hv.x; accH[i][1] += wt * hv.y;               \
            accH[i][2] += wt * hv.z; accH[i][3] += wt * hv.w;               \
            accR[i][0] += wt * rv.x; accR[i][1] += wt * rv.y;               \
            accR[i][2] += wt * rv.z; accR[i][3] += wt * rv.w;               \
        }                                                                   \
    }

// Aggregation: one warp per node, lane owns 4 feature columns. 2-edge unroll
// issues 4 independent 512B feature loads per iteration for latency hiding.
__global__ void __launch_bounds__(256) k_agg(const float* __restrict__ h,
                                             const float* __restrict__ inputr,
                                             float* __restrict__ out) {
    int gtid = blockIdx.x * blockDim.x + threadIdx.x;
    int node = gtid >> 5;
    int lane = threadIdx.x & 31;
    if (node >= NN) return;

    int start = g_offsets[node];
    int end = start + g_counts[node];

    float accH[NH][4];
    float accR[NH][4];
    float rs[NH];
#pragma unroll
    for (int i = 0; i < NH; i++) {
        rs[i] = 0.0f;
#pragma unroll
        for (int k = 0; k < 4; k++) { accH[i][k] = 0.0f; accR[i][k] = 0.0f; }
    }

    int j = start;
#pragma unroll 1
    for (; j + 1 < end; j += 2) {
        int2 sa = g_sr[j];
        int2 sb = g_sr[j + 1];
        float4 ea = g_ee[j];
        float4 eb = g_ee[j + 1];
        float4 ha = *(const float4*)(h + (size_t)sa.x * F + lane * 4);
        float4 ra = *(const float4*)(inputr + (size_t)sa.y * F + lane * 4);
        float4 hb = *(const float4*)(h + (size_t)sb.x * F + lane * 4);
        float4 rb = *(const float4*)(inputr + (size_t)sb.y * F + lane * 4);
        ACCUM(ea, ha, ra);
        ACCUM(eb, hb, rb);
    }
    if (j < end) {
        int2 sa = g_sr[j];
        float4 ea = g_ee[j];
        float4 ha = *(const float4*)(h + (size_t)sa.x * F + lane * 4);
        float4 ra = *(const float4*)(inputr + (size_t)sa.y * F + lane * 4);
        ACCUM(ea, ha, ra);
    }

#pragma unroll
    for (int i = 0; i < NH; i++) {
        float4 cw = *(const float4*)(g_cumw + i * F + lane * 4);
        float inv = 1.0f / rs[i];
        float4 o;
        o.x = (cw.x * accH[i][0] - accR[i][0]) * inv;
        o.y = (cw.y * accH[i][1] - accR[i][1]) * inv;
        o.z = (cw.z * accH[i][2] - accR[i][2]) * inv;
        o.w = (cw.w * accH[i][3] - accR[i][3]) * inv;
        __stcs((float4*)(out + (size_t)i * NN * F + (size_t)node * F + lane * 4), o);
    }
}

extern "C" void kernel_launch(void* const* d_in, const int* in_sizes, int n_in,
                              void* d_out, int out_size) {
    const float* h      = (const float*)d_in[0];
    const float* inputr = (const float*)d_in[1];
    const float* w      = (const float*)d_in[2];
    const float* asd    = (const float*)d_in[3];
    const void*  A      = d_in[4];
    float* out = (float*)d_out;

    k_init<<<(NN + 255) / 256, 256>>>(A, w, asd);
    k_logits_hist<<<NODE_BLOCKS + REL_BLOCKS + HIST_BLOCKS, 256>>>(h, inputr, A);
    k_scan1<<<SCAN_NB, SCAN_B>>>();
    k_scan3<<<SCAN_NB, SCAN_B>>>();
    k_scatter<<<(NE + 255) / 256, 256>>>(A);
    k_agg<<<(NN * 32 + 255) / 256, 256>>>(h, inputr, out);
}